// round 11
// baseline (speedup 1.0000x reference)
#include <cuda_runtime.h>
#include <cstdint>

// x: (128, 32, 2, 64, 64) fp32 -> 4096 tiles of (2, 64, 64).
// plaq[i][j] = t0[i][j] + t1[(i+1)%64][j] - t0[i][(j+1)%64] - t1[i][j]
// out[tile] = mean(cos(plaq))
//
// R9 winner + explicit L2 policy split, fixed for sm_103 ptxas (evict
// modifiers require .v4.b64 width -> 32-byte loads):
//  - t1 (read twice per replay) -> ld.global.nc.L2::evict_last.v4.b64:
//    pins its 64 MB in the 126 MB L2 across graph replays.
//  - t0 (read once) -> __ldcs float4 (evict-first stream), as in R9.
// Thread granularity: 8-float groups, 2 per thread. j+1 roll: 7/8 in-reg,
// 1/8 via lane shuffle (warp = 4 rows x 8 lanes; src=(lane&~7)|((lane+1)&7)).

#define THREADS 256

// 32-byte pinned load: 8 floats as 4 x b64.
__device__ __forceinline__ void ld32_evict_last(const float* p, float* v8) {
    uint64_t a, b, c, d;
    asm volatile("ld.global.nc.L2::evict_last.v4.b64 {%0,%1,%2,%3}, [%4];"
                 : "=l"(a), "=l"(b), "=l"(c), "=l"(d) : "l"(p));
    ((uint64_t*)v8)[0] = a;
    ((uint64_t*)v8)[1] = b;
    ((uint64_t*)v8)[2] = c;
    ((uint64_t*)v8)[3] = d;
}

__global__ __launch_bounds__(THREADS, 8) void plaq_trace_l2pin_kernel(
    const float* __restrict__ x, float* __restrict__ out)
{
    const int t = blockIdx.x;
    const float* __restrict__ t0 = x + (size_t)t * 8192;   // 4096 floats
    const float* __restrict__ t1 = t0 + 4096;

    const int tid  = threadIdx.x;
    const int lane = tid & 31;
    const int wid  = tid >> 5;
    const int src  = (lane & ~7) | ((lane + 1) & 7);  // right lane in 8-lane row seg

    float sum = 0.0f;

    #pragma unroll
    for (int k = 0; k < 2; k++) {
        const int g8 = tid + k * THREADS;        // 8-float group 0..511
        const int i  = g8 >> 3;                  // row 0..63
        const int j8 = g8 & 7;                   // group-in-row
        const int g8r = (((i + 1) & 63) << 3) | j8;

        // t0: two 16B evict-first (streaming) loads
        const float4 A0a = __ldcs((const float4*)(t0 + g8 * 8));
        const float4 A0b = __ldcs((const float4*)(t0 + g8 * 8 + 4));

        // t1: two 32B evict-last (pinned) loads
        float A1[8], B1[8];
        ld32_evict_last(t1 + g8 * 8, A1);
        ld32_evict_last(t1 + g8r * 8, B1);

        const float nx = __shfl_sync(0xFFFFFFFFu, A0a.x, src);

        sum += __cosf(A0a.x + B1[0] - A0a.y - A1[0]);
        sum += __cosf(A0a.y + B1[1] - A0a.z - A1[1]);
        sum += __cosf(A0a.z + B1[2] - A0a.w - A1[2]);
        sum += __cosf(A0a.w + B1[3] - A0b.x - A1[3]);
        sum += __cosf(A0b.x + B1[4] - A0b.y - A1[4]);
        sum += __cosf(A0b.y + B1[5] - A0b.z - A1[5]);
        sum += __cosf(A0b.z + B1[6] - A0b.w - A1[6]);
        sum += __cosf(A0b.w + B1[7] - nx    - A1[7]);
    }

    #pragma unroll
    for (int off = 16; off > 0; off >>= 1)
        sum += __shfl_xor_sync(0xFFFFFFFFu, sum, off);

    __shared__ float warp_sums[THREADS / 32];
    if (lane == 0) warp_sums[wid] = sum;
    __syncthreads();

    if (wid == 0) {
        float s = (lane < (THREADS / 32)) ? warp_sums[lane] : 0.0f;
        #pragma unroll
        for (int off = 4; off > 0; off >>= 1)
            s += __shfl_xor_sync(0xFFFFFFFFu, s, off);
        if (lane == 0) out[t] = s * (1.0f / 4096.0f);
    }
}

extern "C" void kernel_launch(void* const* d_in, const int* in_sizes, int n_in,
                              void* d_out, int out_size)
{
    const float* x = (const float*)d_in[0];
    float* out = (float*)d_out;
    plaq_trace_l2pin_kernel<<<4096, THREADS>>>(x, out);
}